// round 13
// baseline (speedup 1.0000x reference)
#include <cuda_runtime.h>
#include <math.h>

#define BATCH 16
#define SEQ   1024
#define DIM   384
#define NH    6
#define HD    64
#define QKV_COLS (3*DIM)
#define M_TOTAL  (BATCH*SEQ)
#define SCALE_Q  0.125f          // 64^-0.5

typedef unsigned long long u64;

// Scratch (device globals; no allocations allowed)
static __device__ float g_q[(size_t)BATCH*NH*SEQ*HD];     // (B,H,N,hd), pre-scaled by SCALE_Q
static __device__ float g_k[(size_t)BATCH*NH*SEQ*HD];
static __device__ float g_v[(size_t)BATCH*NH*SEQ*HD];
static __device__ float g_att[(size_t)BATCH*SEQ*DIM];     // (B,N,D) attention output

// Packed fp32x2 (Blackwell): (lo,hi) float pair in one aligned register pair.
#define FMA2(c,a,b)   asm("fma.rn.f32x2 %0, %1, %2, %0;" : "+l"(c) : "l"(a), "l"(b))
#define PK2(d,f)      asm("mov.b64 %0, {%1, %1};" : "=l"(d) : "f"(f))
#define UNPK(lo,hi,s) asm("mov.b64 {%0, %1}, %2;" : "=f"(lo), "=f"(hi) : "l"(s))

// ---------------------------------------------------------------------------
// QKV GEMM (R2 structure, f32x2 inner product):
// C = x(16384x384) @ w_qkv(384x1152) + b_qkv, scattered to g_q/g_k/g_v.
// 64x64 block tile, BK=16, 256 threads, 4x4 micro-tile where the 4 columns
// are held as 2 packed f32x2 pairs -> 8 u64 accumulators (16 registers).
// ---------------------------------------------------------------------------
__global__ __launch_bounds__(256, 2)
void qkv_gemm_kernel(const float* __restrict__ x,
                     const float* __restrict__ w,
                     const float* __restrict__ bias)
{
    __shared__ float As[16][68];   // As[k][m]
    __shared__ float Bs[16][68];   // Bs[k][n]
    const int tid = threadIdx.x;
    const int tx = tid & 15, ty = tid >> 4;
    const int bm = blockIdx.x * 64;
    const int bn = blockIdx.y * 64;
    const int arow = tid >> 2;            // 0..63
    const int acol = (tid & 3) << 2;      // 0,4,8,12
    const int brow = tid >> 4;            // 0..15
    const int bcol = (tid & 15) << 2;     // 0..60

    u64 d00=0,d01=0,d10=0,d11=0,d20=0,d21=0,d30=0,d31=0;

    for (int kt = 0; kt < DIM; kt += 16) {
        float4 av = *reinterpret_cast<const float4*>(
            x + (size_t)(bm + arow) * DIM + kt + acol);
        As[acol+0][arow] = av.x; As[acol+1][arow] = av.y;
        As[acol+2][arow] = av.z; As[acol+3][arow] = av.w;
        float4 bv = *reinterpret_cast<const float4*>(
            w + (size_t)(kt + brow) * QKV_COLS + bn + bcol);
        Bs[brow][bcol+0] = bv.x; Bs[brow][bcol+1] = bv.y;
        Bs[brow][bcol+2] = bv.z; Bs[brow][bcol+3] = bv.w;
        __syncthreads();
        #pragma unroll
        for (int k = 0; k < 16; k++) {
            float4 aq = *reinterpret_cast<const float4*>(&As[k][ty*4]);
            ulonglong2 bp = *reinterpret_cast<const ulonglong2*>(&Bs[k][tx*4]);
            u64 a0, a1, a2, a3;
            PK2(a0, aq.x); PK2(a1, aq.y); PK2(a2, aq.z); PK2(a3, aq.w);
            FMA2(d00, a0, bp.x); FMA2(d01, a0, bp.y);
            FMA2(d10, a1, bp.x); FMA2(d11, a1, bp.y);
            FMA2(d20, a2, bp.x); FMA2(d21, a2, bp.y);
            FMA2(d30, a3, bp.x); FMA2(d31, a3, bp.y);
        }
        __syncthreads();
    }

    const int s = bn / DIM;               // 0:q 1:k 2:v
    const int h = (bn % DIM) / HD;
    float* dst = (s == 0) ? g_q : ((s == 1) ? g_k : g_v);
    const float sc = (s == 0) ? SCALE_Q : 1.0f;
    const float b0 = bias[bn + tx*4 + 0];
    const float b1 = bias[bn + tx*4 + 1];
    const float b2 = bias[bn + tx*4 + 2];
    const float b3 = bias[bn + tx*4 + 3];
    #define STQ_ROW(I, DA, DB) do {                                   \
        int m  = bm + ty*4 + I;                                       \
        int b_ = m >> 10;                                             \
        int n_ = m & (SEQ - 1);                                       \
        size_t base = (((size_t)b_ * NH + h) * SEQ + n_) * HD;        \
        float l0, h0, l1, h1;                                         \
        UNPK(l0, h0, DA); UNPK(l1, h1, DB);                           \
        dst[base + tx*4 + 0] = (l0 + b0) * sc;                        \
        dst[base + tx*4 + 1] = (h0 + b1) * sc;                        \
        dst[base + tx*4 + 2] = (l1 + b2) * sc;                        \
        dst[base + tx*4 + 3] = (h1 + b3) * sc;                        \
    } while (0)
    STQ_ROW(0, d00, d01);
    STQ_ROW(1, d10, d11);
    STQ_ROW(2, d20, d21);
    STQ_ROW(3, d30, d31);
    #undef STQ_ROW
}

// ---------------------------------------------------------------------------
// fp32 flash attention — EXACT kernel from R2/R11 (proven pass, twice).
// ---------------------------------------------------------------------------
__global__ __launch_bounds__(256)
void attn_kernel()
{
    extern __shared__ float sm[];
    float* Qs  = sm;                // [64][65]  row=query, col=hd
    float* KPs = sm + 64*65;        // [64][65]  K tile, then reused as P tile
    float* Vs  = sm + 2*64*65;      // [64][65]  row=key,   col=hd

    const int tid = threadIdx.x;
    const int tx = tid & 15, ty = tid >> 4;
    const int bh = blockIdx.y;      // b*NH + h
    const int qt = blockIdx.x;      // query tile

    const float* Qg = g_q + ((size_t)bh * SEQ + qt*64) * HD;
    const float* Kg = g_k + (size_t)bh * SEQ * HD;
    const float* Vg = g_v + (size_t)bh * SEQ * HD;

    #pragma unroll
    for (int r = 0; r < 4; r++) {
        int idx = tid + r*256;
        int row = idx >> 4;
        int c4  = (idx & 15) << 2;
        float4 v = *reinterpret_cast<const float4*>(Qg + row*HD + c4);
        Qs[row*65+c4+0]=v.x; Qs[row*65+c4+1]=v.y;
        Qs[row*65+c4+2]=v.z; Qs[row*65+c4+3]=v.w;
    }

    float mi[4], li[4], o[4][4] = {};
    #pragma unroll
    for (int i = 0; i < 4; i++) { mi[i] = -1e30f; li[i] = 0.0f; }

    for (int t = 0; t < SEQ/64; t++) {
        __syncthreads();
        #pragma unroll
        for (int r = 0; r < 4; r++) {
            int idx = tid + r*256;
            int row = idx >> 4;
            int c4  = (idx & 15) << 2;
            float4 kv = *reinterpret_cast<const float4*>(Kg + (size_t)(t*64+row)*HD + c4);
            KPs[row*65+c4+0]=kv.x; KPs[row*65+c4+1]=kv.y;
            KPs[row*65+c4+2]=kv.z; KPs[row*65+c4+3]=kv.w;
            float4 vv = *reinterpret_cast<const float4*>(Vg + (size_t)(t*64+row)*HD + c4);
            Vs[row*65+c4+0]=vv.x; Vs[row*65+c4+1]=vv.y;
            Vs[row*65+c4+2]=vv.z; Vs[row*65+c4+3]=vv.w;
        }
        __syncthreads();

        float s[4][4] = {};
        #pragma unroll
        for (int k = 0; k < HD; k++) {
            float a[4], b[4];
            #pragma unroll
            for (int i = 0; i < 4; i++) a[i] = Qs[(ty*4+i)*65 + k];
            #pragma unroll
            for (int j = 0; j < 4; j++) b[j] = KPs[(tx*4+j)*65 + k];
            #pragma unroll
            for (int i = 0; i < 4; i++)
                #pragma unroll
                for (int j = 0; j < 4; j++)
                    s[i][j] = fmaf(a[i], b[j], s[i][j]);
        }

        #pragma unroll
        for (int i = 0; i < 4; i++) {
            float rm = fmaxf(fmaxf(s[i][0], s[i][1]), fmaxf(s[i][2], s[i][3]));
            #pragma unroll
            for (int off = 8; off >= 1; off >>= 1)
                rm = fmaxf(rm, __shfl_xor_sync(0xffffffffu, rm, off));
            float mnew  = fmaxf(mi[i], rm);
            float alpha = __expf(mi[i] - mnew);
            float rs = 0.0f;
            #pragma unroll
            for (int j = 0; j < 4; j++) { s[i][j] = __expf(s[i][j] - mnew); rs += s[i][j]; }
            #pragma unroll
            for (int off = 8; off >= 1; off >>= 1)
                rs += __shfl_xor_sync(0xffffffffu, rs, off);
            li[i] = li[i] * alpha + rs;
            mi[i] = mnew;
            #pragma unroll
            for (int j = 0; j < 4; j++) o[i][j] *= alpha;
        }

        __syncthreads();

        #pragma unroll
        for (int i = 0; i < 4; i++)
            #pragma unroll
            for (int j = 0; j < 4; j++)
                KPs[(ty*4+i)*65 + tx*4+j] = s[i][j];
        __syncthreads();

        #pragma unroll
        for (int k = 0; k < 64; k++) {
            float a[4], b[4];
            #pragma unroll
            for (int i = 0; i < 4; i++) a[i] = KPs[(ty*4+i)*65 + k];
            #pragma unroll
            for (int j = 0; j < 4; j++) b[j] = Vs[k*65 + tx*4+j];
            #pragma unroll
            for (int i = 0; i < 4; i++)
                #pragma unroll
                for (int j = 0; j < 4; j++)
                    o[i][j] = fmaf(a[i], b[j], o[i][j]);
        }
    }

    const int b_ = bh / NH, h = bh % NH;
    #pragma unroll
    for (int i = 0; i < 4; i++) {
        float inv = 1.0f / li[i];
        int n = qt*64 + ty*4 + i;
        size_t base = ((size_t)b_ * SEQ + n) * DIM + h*HD;
        #pragma unroll
        for (int j = 0; j < 4; j++)
            g_att[base + tx*4 + j] = o[i][j] * inv;
    }
}

// ---------------------------------------------------------------------------
// Proj GEMM (R2 structure, f32x2 inner product):
// out = g_att(16384x384) @ w_proj(384x384) + b_proj
// ---------------------------------------------------------------------------
__global__ __launch_bounds__(256, 2)
void proj_gemm_kernel(const float* __restrict__ w,
                      const float* __restrict__ bias,
                      float* __restrict__ out)
{
    __shared__ float As[16][68];
    __shared__ float Bs[16][68];
    const int tid = threadIdx.x;
    const int tx = tid & 15, ty = tid >> 4;
    const int bm = blockIdx.x * 64;
    const int bn = blockIdx.y * 64;
    const int arow = tid >> 2;
    const int acol = (tid & 3) << 2;
    const int brow = tid >> 4;
    const int bcol = (tid & 15) << 2;

    u64 d00=0,d01=0,d10=0,d11=0,d20=0,d21=0,d30=0,d31=0;

    for (int kt = 0; kt < DIM; kt += 16) {
        float4 av = *reinterpret_cast<const float4*>(
            g_att + (size_t)(bm + arow) * DIM + kt + acol);
        As[acol+0][arow] = av.x; As[acol+1][arow] = av.y;
        As[acol+2][arow] = av.z; As[acol+3][arow] = av.w;
        float4 bv = *reinterpret_cast<const float4*>(
            w + (size_t)(kt + brow) * DIM + bn + bcol);
        Bs[brow][bcol+0] = bv.x; Bs[brow][bcol+1] = bv.y;
        Bs[brow][bcol+2] = bv.z; Bs[brow][bcol+3] = bv.w;
        __syncthreads();
        #pragma unroll
        for (int k = 0; k < 16; k++) {
            float4 aq = *reinterpret_cast<const float4*>(&As[k][ty*4]);
            ulonglong2 bp = *reinterpret_cast<const ulonglong2*>(&Bs[k][tx*4]);
            u64 a0, a1, a2, a3;
            PK2(a0, aq.x); PK2(a1, aq.y); PK2(a2, aq.z); PK2(a3, aq.w);
            FMA2(d00, a0, bp.x); FMA2(d01, a0, bp.y);
            FMA2(d10, a1, bp.x); FMA2(d11, a1, bp.y);
            FMA2(d20, a2, bp.x); FMA2(d21, a2, bp.y);
            FMA2(d30, a3, bp.x); FMA2(d31, a3, bp.y);
        }
        __syncthreads();
    }

    const float b0 = bias[bn + tx*4 + 0];
    const float b1 = bias[bn + tx*4 + 1];
    const float b2 = bias[bn + tx*4 + 2];
    const float b3 = bias[bn + tx*4 + 3];
    #define STP_ROW(I, DA, DB) do {                                   \
        int m = bm + ty*4 + I;                                        \
        float l0, h0, l1, h1;                                         \
        UNPK(l0, h0, DA); UNPK(l1, h1, DB);                           \
        out[(size_t)m * DIM + bn + tx*4 + 0] = l0 + b0;               \
        out[(size_t)m * DIM + bn + tx*4 + 1] = h0 + b1;               \
        out[(size_t)m * DIM + bn + tx*4 + 2] = l1 + b2;               \
        out[(size_t)m * DIM + bn + tx*4 + 3] = h1 + b3;               \
    } while (0)
    STP_ROW(0, d00, d01);
    STP_ROW(1, d10, d11);
    STP_ROW(2, d20, d21);
    STP_ROW(3, d30, d31);
    #undef STP_ROW
}

// ---------------------------------------------------------------------------

extern "C" void kernel_launch(void* const* d_in, const int* in_sizes, int n_in,
                              void* d_out, int out_size)
{
    const float* x      = (const float*)d_in[0];
    const float* w_qkv  = (const float*)d_in[1];
    const float* b_qkv  = (const float*)d_in[2];
    const float* w_proj = (const float*)d_in[3];
    const float* b_proj = (const float*)d_in[4];
    float* out = (float*)d_out;

    const int attn_smem = 3 * 64 * 65 * sizeof(float);   // 49,920 B
    static bool attr_set = false;
    if (!attr_set) {
        cudaFuncSetAttribute(attn_kernel,
                             cudaFuncAttributeMaxDynamicSharedMemorySize, attn_smem);
        attr_set = true;
    }

    dim3 g1(M_TOTAL/64, QKV_COLS/64);        // 256 x 18
    qkv_gemm_kernel<<<g1, 256>>>(x, w_qkv, b_qkv);

    dim3 g2(SEQ/64, BATCH*NH);               // 16 x 96
    attn_kernel<<<g2, 256, attn_smem>>>();

    dim3 g3(M_TOTAL/64, DIM/64);             // 256 x 6
    proj_gemm_kernel<<<g3, 256>>>(w_proj, b_proj, out);
}

// round 15
// speedup vs baseline: 1.0807x; 1.0807x over previous
#include <cuda_runtime.h>
#include <math.h>

#define BATCH 16
#define SEQ   1024
#define DIM   384
#define NH    6
#define HD    64
#define QKV_COLS (3*DIM)
#define M_TOTAL  (BATCH*SEQ)
#define SCALE_Q  0.125f          // 64^-0.5

typedef unsigned long long u64;

// Scratch (device globals; no allocations allowed)
static __device__ float g_q[(size_t)BATCH*NH*SEQ*HD];     // (B,H,N,hd), pre-scaled by SCALE_Q
static __device__ float g_k[(size_t)BATCH*NH*SEQ*HD];
static __device__ float g_v[(size_t)BATCH*NH*SEQ*HD];
static __device__ float g_att[(size_t)BATCH*SEQ*DIM];     // (B,N,D) attention output

// Packed fp32x2 (Blackwell): (lo,hi) float pair in one aligned register pair.
#define FMA2(c,a,b)   asm("fma.rn.f32x2 %0, %1, %2, %0;" : "+l"(c) : "l"(a), "l"(b))
#define PK2(d,f)      asm("mov.b64 %0, {%1, %1};" : "=l"(d) : "f"(f))
#define UNPK(lo,hi,s) asm("mov.b64 {%0, %1}, %2;" : "=f"(lo), "=f"(hi) : "l"(s))

// ---------------------------------------------------------------------------
// QKV GEMM, f32x2 with m-pairs: C = x @ w_qkv + b_qkv -> g_q/g_k/g_v.
// Tile 128m x 64n, BK=16, 256 threads (16x16), micro 8m x 4n.
// The 8 m-rows are 4 f32x2 pairs loaded natively (ulonglong2) from As[k][m]
// (transposed). 16 u64 accumulators (proven-safe register-pair count).
// Per k: 32 B smem -> 32 FMADD = 1 B/FMA (2x the R2 ratio).
// ---------------------------------------------------------------------------
__global__ __launch_bounds__(256)
void qkv_gemm_kernel(const float* __restrict__ x,
                     const float* __restrict__ w,
                     const float* __restrict__ bias)
{
    __shared__ float As[16][132];   // [k][m] transposed, 128 + pad4 (row = 528 B, 16B-aligned)
    __shared__ float Bs[16][68];    // [k][n], 64 + pad4 (row = 272 B, 16B-aligned)

    const int tid = threadIdx.x;
    const int ty  = tid >> 4, tx = tid & 15;
    const int ty8 = ty * 8, tx4 = tx * 4;
    const int bm  = blockIdx.x * 128, bn = blockIdx.y * 64;

    u64 e00=0,e01=0,e02=0,e03=0;   // m-pair 0, cols 0..3
    u64 e10=0,e11=0,e12=0,e13=0;   // m-pair 1
    u64 e20=0,e21=0,e22=0,e23=0;   // m-pair 2
    u64 e30=0,e31=0,e32=0,e33=0;   // m-pair 3

    const int arow = tid >> 2, akc = (tid & 3) * 4;   // A: 2 float4/thread
    const int brow = tid >> 4, bcol = (tid & 15) * 4; // B: 1 float4/thread

    for (int kt = 0; kt < DIM; kt += 16) {
        float4 va0 = *reinterpret_cast<const float4*>(
            x + (size_t)(bm + arow) * DIM + kt + akc);
        float4 va1 = *reinterpret_cast<const float4*>(
            x + (size_t)(bm + arow + 64) * DIM + kt + akc);
        float4 bv = *reinterpret_cast<const float4*>(
            w + (size_t)(kt + brow) * QKV_COLS + bn + bcol);
        As[akc+0][arow] = va0.x; As[akc+1][arow] = va0.y;
        As[akc+2][arow] = va0.z; As[akc+3][arow] = va0.w;
        As[akc+0][arow+64] = va1.x; As[akc+1][arow+64] = va1.y;
        As[akc+2][arow+64] = va1.z; As[akc+3][arow+64] = va1.w;
        Bs[brow][bcol+0] = bv.x; Bs[brow][bcol+1] = bv.y;
        Bs[brow][bcol+2] = bv.z; Bs[brow][bcol+3] = bv.w;
        __syncthreads();
        #pragma unroll
        for (int k = 0; k < 16; k++) {
            ulonglong2 aA = *reinterpret_cast<const ulonglong2*>(&As[k][ty8]);
            ulonglong2 aB = *reinterpret_cast<const ulonglong2*>(&As[k][ty8 + 4]);
            float4 bq = *reinterpret_cast<const float4*>(&Bs[k][tx4]);
            u64 b0, b1, b2, b3;
            PK2(b0, bq.x); PK2(b1, bq.y); PK2(b2, bq.z); PK2(b3, bq.w);
            FMA2(e00, aA.x, b0); FMA2(e01, aA.x, b1); FMA2(e02, aA.x, b2); FMA2(e03, aA.x, b3);
            FMA2(e10, aA.y, b0); FMA2(e11, aA.y, b1); FMA2(e12, aA.y, b2); FMA2(e13, aA.y, b3);
            FMA2(e20, aB.x, b0); FMA2(e21, aB.x, b1); FMA2(e22, aB.x, b2); FMA2(e23, aB.x, b3);
            FMA2(e30, aB.y, b0); FMA2(e31, aB.y, b1); FMA2(e32, aB.y, b2); FMA2(e33, aB.y, b3);
        }
        __syncthreads();
    }

    const int s = bn / DIM;               // 0:q 1:k 2:v (bn 64-aligned, 64 | 384)
    const int h = (bn % DIM) / HD;
    float* dst = (s == 0) ? g_q : ((s == 1) ? g_k : g_v);
    const float sc = (s == 0) ? SCALE_Q : 1.0f;
    const float b0 = bias[bn + tx4 + 0];
    const float b1 = bias[bn + tx4 + 1];
    const float b2 = bias[bn + tx4 + 2];
    const float b3 = bias[bn + tx4 + 3];
    const int b_ = bm >> 10;                       // 128 | bm, rows stay in one batch
    const int nb = (bm & (SEQ - 1)) + ty8;
    const size_t hb = (size_t)(b_ * NH + h) * SEQ;
    #define STQ(P, CA, CB, CC, CD) do {                               \
        float l0,h0,l1,h1,l2,h2,l3,h3;                                \
        UNPK(l0,h0,CA); UNPK(l1,h1,CB);                               \
        UNPK(l2,h2,CC); UNPK(l3,h3,CD);                               \
        size_t r0 = (hb + nb + 2*P) * HD + tx4;                       \
        dst[r0 + 0]      = (l0 + b0) * sc;                            \
        dst[r0 + 1]      = (l1 + b1) * sc;                            \
        dst[r0 + 2]      = (l2 + b2) * sc;                            \
        dst[r0 + 3]      = (l3 + b3) * sc;                            \
        dst[r0 + HD + 0] = (h0 + b0) * sc;                            \
        dst[r0 + HD + 1] = (h1 + b1) * sc;                            \
        dst[r0 + HD + 2] = (h2 + b2) * sc;                            \
        dst[r0 + HD + 3] = (h3 + b3) * sc;                            \
    } while (0)
    STQ(0, e00, e01, e02, e03);
    STQ(1, e10, e11, e12, e13);
    STQ(2, e20, e21, e22, e23);
    STQ(3, e30, e31, e32, e33);
    #undef STQ
}

// ---------------------------------------------------------------------------
// fp32 flash attention — EXACT kernel from R2/R11/R13 (proven pass, 3x).
// ---------------------------------------------------------------------------
__global__ __launch_bounds__(256)
void attn_kernel()
{
    extern __shared__ float sm[];
    float* Qs  = sm;                // [64][65]  row=query, col=hd
    float* KPs = sm + 64*65;        // [64][65]  K tile, then reused as P tile
    float* Vs  = sm + 2*64*65;      // [64][65]  row=key,   col=hd

    const int tid = threadIdx.x;
    const int tx = tid & 15, ty = tid >> 4;
    const int bh = blockIdx.y;      // b*NH + h
    const int qt = blockIdx.x;      // query tile

    const float* Qg = g_q + ((size_t)bh * SEQ + qt*64) * HD;
    const float* Kg = g_k + (size_t)bh * SEQ * HD;
    const float* Vg = g_v + (size_t)bh * SEQ * HD;

    #pragma unroll
    for (int r = 0; r < 4; r++) {
        int idx = tid + r*256;
        int row = idx >> 4;
        int c4  = (idx & 15) << 2;
        float4 v = *reinterpret_cast<const float4*>(Qg + row*HD + c4);
        Qs[row*65+c4+0]=v.x; Qs[row*65+c4+1]=v.y;
        Qs[row*65+c4+2]=v.z; Qs[row*65+c4+3]=v.w;
    }

    float mi[4], li[4], o[4][4] = {};
    #pragma unroll
    for (int i = 0; i < 4; i++) { mi[i] = -1e30f; li[i] = 0.0f; }

    for (int t = 0; t < SEQ/64; t++) {
        __syncthreads();
        #pragma unroll
        for (int r = 0; r < 4; r++) {
            int idx = tid + r*256;
            int row = idx >> 4;
            int c4  = (idx & 15) << 2;
            float4 kv = *reinterpret_cast<const float4*>(Kg + (size_t)(t*64+row)*HD + c4);
            KPs[row*65+c4+0]=kv.x; KPs[row*65+c4+1]=kv.y;
            KPs[row*65+c4+2]=kv.z; KPs[row*65+c4+3]=kv.w;
            float4 vv = *reinterpret_cast<const float4*>(Vg + (size_t)(t*64+row)*HD + c4);
            Vs[row*65+c4+0]=vv.x; Vs[row*65+c4+1]=vv.y;
            Vs[row*65+c4+2]=vv.z; Vs[row*65+c4+3]=vv.w;
        }
        __syncthreads();

        float s[4][4] = {};
        #pragma unroll
        for (int k = 0; k < HD; k++) {
            float a[4], b[4];
            #pragma unroll
            for (int i = 0; i < 4; i++) a[i] = Qs[(ty*4+i)*65 + k];
            #pragma unroll
            for (int j = 0; j < 4; j++) b[j] = KPs[(tx*4+j)*65 + k];
            #pragma unroll
            for (int i = 0; i < 4; i++)
                #pragma unroll
                for (int j = 0; j < 4; j++)
                    s[i][j] = fmaf(a[i], b[j], s[i][j]);
        }

        #pragma unroll
        for (int i = 0; i < 4; i++) {
            float rm = fmaxf(fmaxf(s[i][0], s[i][1]), fmaxf(s[i][2], s[i][3]));
            #pragma unroll
            for (int off = 8; off >= 1; off >>= 1)
                rm = fmaxf(rm, __shfl_xor_sync(0xffffffffu, rm, off));
            float mnew  = fmaxf(mi[i], rm);
            float alpha = __expf(mi[i] - mnew);
            float rs = 0.0f;
            #pragma unroll
            for (int j = 0; j < 4; j++) { s[i][j] = __expf(s[i][j] - mnew); rs += s[i][j]; }
            #pragma unroll
            for (int off = 8; off >= 1; off >>= 1)
                rs += __shfl_xor_sync(0xffffffffu, rs, off);
            li[i] = li[i] * alpha + rs;
            mi[i] = mnew;
            #pragma unroll
            for (int j = 0; j < 4; j++) o[i][j] *= alpha;
        }

        __syncthreads();

        #pragma unroll
        for (int i = 0; i < 4; i++)
            #pragma unroll
            for (int j = 0; j < 4; j++)
                KPs[(ty*4+i)*65 + tx*4+j] = s[i][j];
        __syncthreads();

        #pragma unroll
        for (int k = 0; k < 64; k++) {
            float a[4], b[4];
            #pragma unroll
            for (int i = 0; i < 4; i++) a[i] = KPs[(ty*4+i)*65 + k];
            #pragma unroll
            for (int j = 0; j < 4; j++) b[j] = Vs[k*65 + tx*4+j];
            #pragma unroll
            for (int i = 0; i < 4; i++)
                #pragma unroll
                for (int j = 0; j < 4; j++)
                    o[i][j] = fmaf(a[i], b[j], o[i][j]);
        }
    }

    const int b_ = bh / NH, h = bh % NH;
    #pragma unroll
    for (int i = 0; i < 4; i++) {
        float inv = 1.0f / li[i];
        int n = qt*64 + ty*4 + i;
        size_t base = ((size_t)b_ * SEQ + n) * DIM + h*HD;
        #pragma unroll
        for (int j = 0; j < 4; j++)
            g_att[base + tx*4 + j] = o[i][j] * inv;
    }
}

// ---------------------------------------------------------------------------
// Proj GEMM, same f32x2 m-pair design: out = g_att @ w_proj + b_proj.
// Tile 128m x 64n, BK=16, 256 threads, micro 8m x 4n, 16 u64 accumulators.
// ---------------------------------------------------------------------------
__global__ __launch_bounds__(256)
void proj_gemm_kernel(const float* __restrict__ w,
                      const float* __restrict__ bias,
                      float* __restrict__ out)
{
    __shared__ float As[16][132];
    __shared__ float Bs[16][68];

    const int tid = threadIdx.x;
    const int ty  = tid >> 4, tx = tid & 15;
    const int ty8 = ty * 8, tx4 = tx * 4;
    const int bm  = blockIdx.x * 128, bn = blockIdx.y * 64;

    u64 e00=0,e01=0,e02=0,e03=0;
    u64 e10=0,e11=0,e12=0,e13=0;
    u64 e20=0,e21=0,e22=0,e23=0;
    u64 e30=0,e31=0,e32=0,e33=0;

    const int arow = tid >> 2, akc = (tid & 3) * 4;
    const int brow = tid >> 4, bcol = (tid & 15) * 4;

    for (int kt = 0; kt < DIM; kt += 16) {
        float4 va0 = *reinterpret_cast<const float4*>(
            g_att + (size_t)(bm + arow) * DIM + kt + akc);
        float4 va1 = *reinterpret_cast<const float4*>(
            g_att + (size_t)(bm + arow + 64) * DIM + kt + akc);
        float4 bv = *reinterpret_cast<const float4*>(
            w + (size_t)(kt + brow) * DIM + bn + bcol);
        As[akc+0][arow] = va0.x; As[akc+1][arow] = va0.y;
        As[akc+2][arow] = va0.z; As[akc+3][arow] = va0.w;
        As[akc+0][arow+64] = va1.x; As[akc+1][arow+64] = va1.y;
        As[akc+2][arow+64] = va1.z; As[akc+3][arow+64] = va1.w;
        Bs[brow][bcol+0] = bv.x; Bs[brow][bcol+1] = bv.y;
        Bs[brow][bcol+2] = bv.z; Bs[brow][bcol+3] = bv.w;
        __syncthreads();
        #pragma unroll
        for (int k = 0; k < 16; k++) {
            ulonglong2 aA = *reinterpret_cast<const ulonglong2*>(&As[k][ty8]);
            ulonglong2 aB = *reinterpret_cast<const ulonglong2*>(&As[k][ty8 + 4]);
            float4 bq = *reinterpret_cast<const float4*>(&Bs[k][tx4]);
            u64 b0, b1, b2, b3;
            PK2(b0, bq.x); PK2(b1, bq.y); PK2(b2, bq.z); PK2(b3, bq.w);
            FMA2(e00, aA.x, b0); FMA2(e01, aA.x, b1); FMA2(e02, aA.x, b2); FMA2(e03, aA.x, b3);
            FMA2(e10, aA.y, b0); FMA2(e11, aA.y, b1); FMA2(e12, aA.y, b2); FMA2(e13, aA.y, b3);
            FMA2(e20, aB.x, b0); FMA2(e21, aB.x, b1); FMA2(e22, aB.x, b2); FMA2(e23, aB.x, b3);
            FMA2(e30, aB.y, b0); FMA2(e31, aB.y, b1); FMA2(e32, aB.y, b2); FMA2(e33, aB.y, b3);
        }
        __syncthreads();
    }

    const float b0 = bias[bn + tx4 + 0];
    const float b1 = bias[bn + tx4 + 1];
    const float b2 = bias[bn + tx4 + 2];
    const float b3 = bias[bn + tx4 + 3];
    #define STP(P, CA, CB, CC, CD) do {                               \
        float l0,h0,l1,h1,l2,h2,l3,h3;                                \
        UNPK(l0,h0,CA); UNPK(l1,h1,CB);                               \
        UNPK(l2,h2,CC); UNPK(l3,h3,CD);                               \
        size_t r0 = (size_t)(bm + ty8 + 2*P) * DIM + bn + tx4;        \
        out[r0 + 0]       = l0 + b0;                                  \
        out[r0 + 1]       = l1 + b1;                                  \
        out[r0 + 2]       = l2 + b2;                                  \
        out[r0 + 3]       = l3 + b3;                                  \
        out[r0 + DIM + 0] = h0 + b0;                                  \
        out[r0 + DIM + 1] = h1 + b1;                                  \
        out[r0 + DIM + 2] = h2 + b2;                                  \
        out[r0 + DIM + 3] = h3 + b3;                                  \
    } while (0)
    STP(0, e00, e01, e02, e03);
    STP(1, e10, e11, e12, e13);
    STP(2, e20, e21, e22, e23);
    STP(3, e30, e31, e32, e33);
    #undef STP
}

// ---------------------------------------------------------------------------

extern "C" void kernel_launch(void* const* d_in, const int* in_sizes, int n_in,
                              void* d_out, int out_size)
{
    const float* x      = (const float*)d_in[0];
    const float* w_qkv  = (const float*)d_in[1];
    const float* b_qkv  = (const float*)d_in[2];
    const float* w_proj = (const float*)d_in[3];
    const float* b_proj = (const float*)d_in[4];
    float* out = (float*)d_out;

    const int attn_smem = 3 * 64 * 65 * sizeof(float);   // 49,920 B
    static bool attr_set = false;
    if (!attr_set) {
        cudaFuncSetAttribute(attn_kernel,
                             cudaFuncAttributeMaxDynamicSharedMemorySize, attn_smem);
        attr_set = true;
    }

    dim3 g1(M_TOTAL/128, QKV_COLS/64);       // 128 x 18
    qkv_gemm_kernel<<<g1, 256>>>(x, w_qkv, b_qkv);

    dim3 g2(SEQ/64, BATCH*NH);               // 16 x 96
    attn_kernel<<<g2, 256, attn_smem>>>();

    dim3 g3(M_TOTAL/128, DIM/64);            // 128 x 6
    proj_gemm_kernel<<<g3, 256>>>(w_proj, b_proj, out);
}

// round 17
// speedup vs baseline: 1.0946x; 1.0129x over previous
#include <cuda_runtime.h>
#include <math.h>

#define BATCH 16
#define SEQ   1024
#define DIM   384
#define NH    6
#define HD    64
#define QKV_COLS (3*DIM)
#define M_TOTAL  (BATCH*SEQ)
#define SCALE_Q  0.125f          // 64^-0.5

typedef unsigned long long u64;

// Scratch (device globals; no allocations allowed)
static __device__ float g_q[(size_t)BATCH*NH*SEQ*HD];     // (B,H,N,hd), pre-scaled by SCALE_Q
static __device__ float g_k[(size_t)BATCH*NH*SEQ*HD];
static __device__ float g_v[(size_t)BATCH*NH*SEQ*HD];
static __device__ float g_att[(size_t)BATCH*SEQ*DIM];     // (B,N,D) attention output

// Packed fp32x2 (Blackwell): (lo,hi) float pair in one aligned register pair.
#define FMA2(c,a,b)   asm("fma.rn.f32x2 %0, %1, %2, %0;" : "+l"(c) : "l"(a), "l"(b))
#define PK2(d,f)      asm("mov.b64 %0, {%1, %1};" : "=l"(d) : "f"(f))
#define UNPK(lo,hi,s) asm("mov.b64 {%0, %1}, %2;" : "=f"(lo), "=f"(hi) : "l"(s))

// ---------------------------------------------------------------------------
// QKV GEMM, f32x2 with m-pairs (EXACT R15 kernel — proven 338us).
// ---------------------------------------------------------------------------
__global__ __launch_bounds__(256)
void qkv_gemm_kernel(const float* __restrict__ x,
                     const float* __restrict__ w,
                     const float* __restrict__ bias)
{
    __shared__ float As[16][132];
    __shared__ float Bs[16][68];

    const int tid = threadIdx.x;
    const int ty  = tid >> 4, tx = tid & 15;
    const int ty8 = ty * 8, tx4 = tx * 4;
    const int bm  = blockIdx.x * 128, bn = blockIdx.y * 64;

    u64 e00=0,e01=0,e02=0,e03=0;
    u64 e10=0,e11=0,e12=0,e13=0;
    u64 e20=0,e21=0,e22=0,e23=0;
    u64 e30=0,e31=0,e32=0,e33=0;

    const int arow = tid >> 2, akc = (tid & 3) * 4;
    const int brow = tid >> 4, bcol = (tid & 15) * 4;

    for (int kt = 0; kt < DIM; kt += 16) {
        float4 va0 = *reinterpret_cast<const float4*>(
            x + (size_t)(bm + arow) * DIM + kt + akc);
        float4 va1 = *reinterpret_cast<const float4*>(
            x + (size_t)(bm + arow + 64) * DIM + kt + akc);
        float4 bv = *reinterpret_cast<const float4*>(
            w + (size_t)(kt + brow) * QKV_COLS + bn + bcol);
        As[akc+0][arow] = va0.x; As[akc+1][arow] = va0.y;
        As[akc+2][arow] = va0.z; As[akc+3][arow] = va0.w;
        As[akc+0][arow+64] = va1.x; As[akc+1][arow+64] = va1.y;
        As[akc+2][arow+64] = va1.z; As[akc+3][arow+64] = va1.w;
        Bs[brow][bcol+0] = bv.x; Bs[brow][bcol+1] = bv.y;
        Bs[brow][bcol+2] = bv.z; Bs[brow][bcol+3] = bv.w;
        __syncthreads();
        #pragma unroll
        for (int k = 0; k < 16; k++) {
            ulonglong2 aA = *reinterpret_cast<const ulonglong2*>(&As[k][ty8]);
            ulonglong2 aB = *reinterpret_cast<const ulonglong2*>(&As[k][ty8 + 4]);
            float4 bq = *reinterpret_cast<const float4*>(&Bs[k][tx4]);
            u64 b0, b1, b2, b3;
            PK2(b0, bq.x); PK2(b1, bq.y); PK2(b2, bq.z); PK2(b3, bq.w);
            FMA2(e00, aA.x, b0); FMA2(e01, aA.x, b1); FMA2(e02, aA.x, b2); FMA2(e03, aA.x, b3);
            FMA2(e10, aA.y, b0); FMA2(e11, aA.y, b1); FMA2(e12, aA.y, b2); FMA2(e13, aA.y, b3);
            FMA2(e20, aB.x, b0); FMA2(e21, aB.x, b1); FMA2(e22, aB.x, b2); FMA2(e23, aB.x, b3);
            FMA2(e30, aB.y, b0); FMA2(e31, aB.y, b1); FMA2(e32, aB.y, b2); FMA2(e33, aB.y, b3);
        }
        __syncthreads();
    }

    const int s = bn / DIM;
    const int h = (bn % DIM) / HD;
    float* dst = (s == 0) ? g_q : ((s == 1) ? g_k : g_v);
    const float sc = (s == 0) ? SCALE_Q : 1.0f;
    const float b0 = bias[bn + tx4 + 0];
    const float b1 = bias[bn + tx4 + 1];
    const float b2 = bias[bn + tx4 + 2];
    const float b3 = bias[bn + tx4 + 3];
    const int b_ = bm >> 10;
    const int nb = (bm & (SEQ - 1)) + ty8;
    const size_t hb = (size_t)(b_ * NH + h) * SEQ;
    #define STQ(P, CA, CB, CC, CD) do {                               \
        float l0,h0,l1,h1,l2,h2,l3,h3;                                \
        UNPK(l0,h0,CA); UNPK(l1,h1,CB);                               \
        UNPK(l2,h2,CC); UNPK(l3,h3,CD);                               \
        size_t r0 = (hb + nb + 2*P) * HD + tx4;                       \
        dst[r0 + 0]      = (l0 + b0) * sc;                            \
        dst[r0 + 1]      = (l1 + b1) * sc;                            \
        dst[r0 + 2]      = (l2 + b2) * sc;                            \
        dst[r0 + 3]      = (l3 + b3) * sc;                            \
        dst[r0 + HD + 0] = (h0 + b0) * sc;                            \
        dst[r0 + HD + 1] = (h1 + b1) * sc;                            \
        dst[r0 + HD + 2] = (h2 + b2) * sc;                            \
        dst[r0 + HD + 3] = (h3 + b3) * sc;                            \
    } while (0)
    STQ(0, e00, e01, e02, e03);
    STQ(1, e10, e11, e12, e13);
    STQ(2, e20, e21, e22, e23);
    STQ(3, e30, e31, e32, e33);
    #undef STQ
}

// ---------------------------------------------------------------------------
// f32x2 flash attention: 64q x 64key tile, 256 threads (ty 0..15 x tx 0..15).
// S micro 4q x 4key (key-pairs, 8 u64); PV micro 4q x 4hd (hd-pairs, 8 u64).
// Max 16 live register pairs (proven-safe). KT transposed at tile load
// (conflict-free STS); KT buffer reused for P. Softmax as R2.
// Smem: Qs[64][68], KT/Ps[64][68], Vs[64][68] = 52,224 B.
// ---------------------------------------------------------------------------
__global__ __launch_bounds__(256)
void attn_kernel()
{
    extern __shared__ float sm[];
    float (*Qs)[68] = reinterpret_cast<float(*)[68]>(sm);             // [q][hd]
    float (*KT)[68] = reinterpret_cast<float(*)[68]>(sm + 64 * 68);   // [hd][key], then P[q][key]
    float (*Vs)[68] = reinterpret_cast<float(*)[68]>(sm + 2 * 64 * 68); // [key][hd]
    float* Ps = &KT[0][0];

    const int tid = threadIdx.x;
    const int ty = tid >> 4, tx = tid & 15;
    const int ty4 = ty * 4, tx4 = tx * 4;
    const int bh = blockIdx.y;      // b*NH + h
    const int qt = blockIdx.x;      // query tile

    const float* Qg = g_q + ((size_t)bh * SEQ + qt*64) * HD;
    const float* Kg = g_k + (size_t)bh * SEQ * HD;
    const float* Vg = g_v + (size_t)bh * SEQ * HD;

    // Load Q tile (pre-scaled), [q][hd] direct
    #pragma unroll
    for (int p = 0; p < 4; p++) {
        int idx = tid + p*256;
        int row = idx >> 4;
        int c4  = (idx & 15) << 2;
        *reinterpret_cast<float4*>(&Qs[row][c4]) =
            *reinterpret_cast<const float4*>(Qg + row*HD + c4);
    }

    float mi[4], li[4];
    #pragma unroll
    for (int i = 0; i < 4; i++) { mi[i] = -1e30f; li[i] = 0.0f; }
    u64 o00=0,o01=0,o10=0,o11=0,o20=0,o21=0,o30=0,o31=0;  // [row i][hd-pair]

    for (int t = 0; t < SEQ/64; t++) {
        __syncthreads();   // prior PV done with Ps/Vs
        // KT: transposed K tile. krow varies within warp -> conflict-free STS.
        // Vs: direct copy.
        #pragma unroll
        for (int p = 0; p < 4; p++) {
            int idx = tid + p*256;
            int krow = idx & 63;            // key
            int kc4  = ((idx >> 6) & 15) << 2;  // hd group
            float4 kv = *reinterpret_cast<const float4*>(
                Kg + (size_t)(t*64 + krow)*HD + kc4);
            KT[kc4+0][krow] = kv.x; KT[kc4+1][krow] = kv.y;
            KT[kc4+2][krow] = kv.z; KT[kc4+3][krow] = kv.w;

            int vrow = idx >> 4;
            int vc4  = (idx & 15) << 2;
            *reinterpret_cast<float4*>(&Vs[vrow][vc4]) =
                *reinterpret_cast<const float4*>(
                    Vg + (size_t)(t*64 + vrow)*HD + vc4);
        }
        __syncthreads();

        // ---- S = Q @ K^T : 4 rows x 2 key-pairs, f32x2 ----
        u64 s00=0,s01=0,s10=0,s11=0,s20=0,s21=0,s30=0,s31=0;
        #pragma unroll 8
        for (int k = 0; k < HD; k++) {
            float a0f = Qs[ty4+0][k];
            float a1f = Qs[ty4+1][k];
            float a2f = Qs[ty4+2][k];
            float a3f = Qs[ty4+3][k];
            u64 a0, a1, a2, a3;
            PK2(a0, a0f); PK2(a1, a1f); PK2(a2, a2f); PK2(a3, a3f);
            ulonglong2 bp = *reinterpret_cast<const ulonglong2*>(&KT[k][tx4]);
            FMA2(s00, a0, bp.x); FMA2(s01, a0, bp.y);
            FMA2(s10, a1, bp.x); FMA2(s11, a1, bp.y);
            FMA2(s20, a2, bp.x); FMA2(s21, a2, bp.y);
            FMA2(s30, a3, bp.x); FMA2(s31, a3, bp.y);
        }

        // ---- online softmax per row; exp'd P kept in locals ----
        float pv[4][4];
        #pragma unroll
        for (int i = 0; i < 4; i++) {
            float f0, f1, f2, f3;
            if (i == 0) { UNPK(f0, f1, s00); UNPK(f2, f3, s01); }
            else if (i == 1) { UNPK(f0, f1, s10); UNPK(f2, f3, s11); }
            else if (i == 2) { UNPK(f0, f1, s20); UNPK(f2, f3, s21); }
            else { UNPK(f0, f1, s30); UNPK(f2, f3, s31); }
            float rm = fmaxf(fmaxf(f0, f1), fmaxf(f2, f3));
            #pragma unroll
            for (int off = 8; off >= 1; off >>= 1)
                rm = fmaxf(rm, __shfl_xor_sync(0xffffffffu, rm, off));
            float mnew  = fmaxf(mi[i], rm);
            float alpha = __expf(mi[i] - mnew);
            f0 = __expf(f0 - mnew); f1 = __expf(f1 - mnew);
            f2 = __expf(f2 - mnew); f3 = __expf(f3 - mnew);
            float rs = (f0 + f1) + (f2 + f3);
            #pragma unroll
            for (int off = 8; off >= 1; off >>= 1)
                rs += __shfl_xor_sync(0xffffffffu, rs, off);
            li[i] = li[i] * alpha + rs;
            mi[i] = mnew;
            u64 al2; PK2(al2, alpha);
            if (i == 0) { asm("mul.rn.f32x2 %0, %0, %1;" : "+l"(o00) : "l"(al2));
                          asm("mul.rn.f32x2 %0, %0, %1;" : "+l"(o01) : "l"(al2)); }
            else if (i == 1) { asm("mul.rn.f32x2 %0, %0, %1;" : "+l"(o10) : "l"(al2));
                               asm("mul.rn.f32x2 %0, %0, %1;" : "+l"(o11) : "l"(al2)); }
            else if (i == 2) { asm("mul.rn.f32x2 %0, %0, %1;" : "+l"(o20) : "l"(al2));
                               asm("mul.rn.f32x2 %0, %0, %1;" : "+l"(o21) : "l"(al2)); }
            else { asm("mul.rn.f32x2 %0, %0, %1;" : "+l"(o30) : "l"(al2));
                   asm("mul.rn.f32x2 %0, %0, %1;" : "+l"(o31) : "l"(al2)); }
            pv[i][0] = f0; pv[i][1] = f1; pv[i][2] = f2; pv[i][3] = f3;
        }

        __syncthreads();   // all warps done reading KT before P overwrite

        #pragma unroll
        for (int i = 0; i < 4; i++)
            *reinterpret_cast<float4*>(Ps + (ty4+i)*68 + tx4) =
                make_float4(pv[i][0], pv[i][1], pv[i][2], pv[i][3]);
        __syncthreads();

        // ---- O += P @ V : 4 rows x 2 hd-pairs, f32x2 ----
        #pragma unroll 8
        for (int kk = 0; kk < 64; kk++) {
            float p0f = Ps[(ty4+0)*68 + kk];
            float p1f = Ps[(ty4+1)*68 + kk];
            float p2f = Ps[(ty4+2)*68 + kk];
            float p3f = Ps[(ty4+3)*68 + kk];
            u64 p0, p1, p2, p3;
            PK2(p0, p0f); PK2(p1, p1f); PK2(p2, p2f); PK2(p3, p3f);
            ulonglong2 vp = *reinterpret_cast<const ulonglong2*>(&Vs[kk][tx4]);
            FMA2(o00, p0, vp.x); FMA2(o01, p0, vp.y);
            FMA2(o10, p1, vp.x); FMA2(o11, p1, vp.y);
            FMA2(o20, p2, vp.x); FMA2(o21, p2, vp.y);
            FMA2(o30, p3, vp.x); FMA2(o31, p3, vp.y);
        }
    }

    // Normalize + write (B,N,D)
    const int b_ = bh / NH, h = bh % NH;
    #pragma unroll
    for (int i = 0; i < 4; i++) {
        float inv = 1.0f / li[i];
        float f0, f1, f2, f3;
        if (i == 0) { UNPK(f0, f1, o00); UNPK(f2, f3, o01); }
        else if (i == 1) { UNPK(f0, f1, o10); UNPK(f2, f3, o11); }
        else if (i == 2) { UNPK(f0, f1, o20); UNPK(f2, f3, o21); }
        else { UNPK(f0, f1, o30); UNPK(f2, f3, o31); }
        int n = qt*64 + ty4 + i;
        size_t base = ((size_t)b_ * SEQ + n) * DIM + h*HD + tx4;
        *reinterpret_cast<float4*>(g_att + base) =
            make_float4(f0*inv, f1*inv, f2*inv, f3*inv);
    }
}

// ---------------------------------------------------------------------------
// Proj GEMM, f32x2 m-pairs (EXACT R15 kernel).
// ---------------------------------------------------------------------------
__global__ __launch_bounds__(256)
void proj_gemm_kernel(const float* __restrict__ w,
                      const float* __restrict__ bias,
                      float* __restrict__ out)
{
    __shared__ float As[16][132];
    __shared__ float Bs[16][68];

    const int tid = threadIdx.x;
    const int ty  = tid >> 4, tx = tid & 15;
    const int ty8 = ty * 8, tx4 = tx * 4;
    const int bm  = blockIdx.x * 128, bn = blockIdx.y * 64;

    u64 e00=0,e01=0,e02=0,e03=0;
    u64 e10=0,e11=0,e12=0,e13=0;
    u64 e20=0,e21=0,e22=0,e23=0;
    u64 e30=0,e31=0,e32=0,e33=0;

    const int arow = tid >> 2, akc = (tid & 3) * 4;
    const int brow = tid >> 4, bcol = (tid & 15) * 4;

    for (int kt = 0; kt < DIM; kt += 16) {
        float4 va0 = *reinterpret_cast<const float4*>(
            g_att + (size_t)(bm + arow) * DIM + kt + akc);
        float4 va1 = *reinterpret_cast<const float4*>(
            g_att + (size_t)(bm + arow + 64) * DIM + kt + akc);
        float4 bv = *reinterpret_cast<const float4*>(
            w + (size_t)(kt + brow) * DIM + bn + bcol);
        As[akc+0][arow] = va0.x; As[akc+1][arow] = va0.y;
        As[akc+2][arow] = va0.z; As[akc+3][arow] = va0.w;
        As[akc+0][arow+64] = va1.x; As[akc+1][arow+64] = va1.y;
        As[akc+2][arow+64] = va1.z; As[akc+3][arow+64] = va1.w;
        Bs[brow][bcol+0] = bv.x; Bs[brow][bcol+1] = bv.y;
        Bs[brow][bcol+2] = bv.z; Bs[brow][bcol+3] = bv.w;
        __syncthreads();
        #pragma unroll
        for (int k = 0; k < 16; k++) {
            ulonglong2 aA = *reinterpret_cast<const ulonglong2*>(&As[k][ty8]);
            ulonglong2 aB = *reinterpret_cast<const ulonglong2*>(&As[k][ty8 + 4]);
            float4 bq = *reinterpret_cast<const float4*>(&Bs[k][tx4]);
            u64 b0, b1, b2, b3;
            PK2(b0, bq.x); PK2(b1, bq.y); PK2(b2, bq.z); PK2(b3, bq.w);
            FMA2(e00, aA.x, b0); FMA2(e01, aA.x, b1); FMA2(e02, aA.x, b2); FMA2(e03, aA.x, b3);
            FMA2(e10, aA.y, b0); FMA2(e11, aA.y, b1); FMA2(e12, aA.y, b2); FMA2(e13, aA.y, b3);
            FMA2(e20, aB.x, b0); FMA2(e21, aB.x, b1); FMA2(e22, aB.x, b2); FMA2(e23, aB.x, b3);
            FMA2(e30, aB.y, b0); FMA2(e31, aB.y, b1); FMA2(e32, aB.y, b2); FMA2(e33, aB.y, b3);
        }
        __syncthreads();
    }

    const float b0 = bias[bn + tx4 + 0];
    const float b1 = bias[bn + tx4 + 1];
    const float b2 = bias[bn + tx4 + 2];
    const float b3 = bias[bn + tx4 + 3];
    #define STP(P, CA, CB, CC, CD) do {                               \
        float l0,h0,l1,h1,l2,h2,l3,h3;                                \
        UNPK(l0,h0,CA); UNPK(l1,h1,CB);                               \
        UNPK(l2,h2,CC); UNPK(l3,h3,CD);                               \
        size_t r0 = (size_t)(bm + ty8 + 2*P) * DIM + bn + tx4;        \
        out[r0 + 0]       = l0 + b0;                                  \
        out[r0 + 1]       = l1 + b1;                                  \
        out[r0 + 2]       = l2 + b2;                                  \
        out[r0 + 3]       = l3 + b3;                                  \
        out[r0 + DIM + 0] = h0 + b0;                                  \
        out[r0 + DIM + 1] = h1 + b1;                                  \
        out[r0 + DIM + 2] = h2 + b2;                                  \
        out[r0 + DIM + 3] = h3 + b3;                                  \
    } while (0)
    STP(0, e00, e01, e02, e03);
    STP(1, e10, e11, e12, e13);
    STP(2, e20, e21, e22, e23);
    STP(3, e30, e31, e32, e33);
    #undef STP
}

// ---------------------------------------------------------------------------

extern "C" void kernel_launch(void* const* d_in, const int* in_sizes, int n_in,
                              void* d_out, int out_size)
{
    const float* x      = (const float*)d_in[0];
    const float* w_qkv  = (const float*)d_in[1];
    const float* b_qkv  = (const float*)d_in[2];
    const float* w_proj = (const float*)d_in[3];
    const float* b_proj = (const float*)d_in[4];
    float* out = (float*)d_out;

    const int attn_smem = 3 * 64 * 68 * sizeof(float);   // 52,224 B
    static bool attr_set = false;
    if (!attr_set) {
        cudaFuncSetAttribute(attn_kernel,
                             cudaFuncAttributeMaxDynamicSharedMemorySize, attn_smem);
        attr_set = true;
    }

    dim3 g1(M_TOTAL/128, QKV_COLS/64);       // 128 x 18
    qkv_gemm_kernel<<<g1, 256>>>(x, w_qkv, b_qkv);

    dim3 g2(SEQ/64, BATCH*NH);               // 16 x 96
    attn_kernel<<<g2, 256, attn_smem>>>();

    dim3 g3(M_TOTAL/128, DIM/64);            // 128 x 6
    proj_gemm_kernel<<<g3, 256>>>(w_proj, b_proj, out);
}